// round 1
// baseline (speedup 1.0000x reference)
#include <cuda_runtime.h>
#include <cuda_bf16.h>
#include <cstdint>

// Problem constants
#define BB 32
#define NS 262144
#define HH 256
#define WW 256
#define HWSZ (HH * WW)

// Per-batch bounds scratch: [b][0]=xmin,[1]=xmax,[2]=ymin,[3]=ymax (order-encoded uints)
__device__ unsigned g_bounds[BB][4];

// Order-preserving float<->uint encoding (works for any sign)
__device__ __forceinline__ unsigned f2o(float f) {
    unsigned u = __float_as_uint(f);
    return (u & 0x80000000u) ? ~u : (u | 0x80000000u);
}
__device__ __forceinline__ float o2f(unsigned u) {
    return __uint_as_float((u & 0x80000000u) ? (u & 0x7fffffffu) : ~u);
}

__global__ void init_bounds_kernel() {
    int b = threadIdx.x;
    if (b < BB) {
        g_bounds[b][0] = 0xFFFFFFFFu;  // min slot (encoded) -> +inf
        g_bounds[b][1] = 0u;           // max slot (encoded) -> -inf
        g_bounds[b][2] = 0xFFFFFFFFu;
        g_bounds[b][3] = 0u;
    }
}

// grid = (8, B), block = 256. Each block reduces 1/8 of both channels of one batch.
__global__ void minmax_kernel(const float* __restrict__ spatial) {
    const int b = blockIdx.y;
    const int seg = blockIdx.x;          // 0..7
    const int seg_elems = HWSZ / 8;      // 8192 floats
    const float* sxp = spatial + (size_t)b * 2 * HWSZ + (size_t)seg * seg_elems;
    const float* syp = sxp + HWSZ;

    float xmn = 3.4e38f, xmx = -3.4e38f, ymn = 3.4e38f, ymx = -3.4e38f;

    const float4* vx = reinterpret_cast<const float4*>(sxp);
    const float4* vy = reinterpret_cast<const float4*>(syp);
    const int nvec = seg_elems / 4;      // 2048

    for (int i = threadIdx.x; i < nvec; i += blockDim.x) {
        float4 a = vx[i];
        xmn = fminf(xmn, fminf(fminf(a.x, a.y), fminf(a.z, a.w)));
        xmx = fmaxf(xmx, fmaxf(fmaxf(a.x, a.y), fmaxf(a.z, a.w)));
        float4 c = vy[i];
        ymn = fminf(ymn, fminf(fminf(c.x, c.y), fminf(c.z, c.w)));
        ymx = fmaxf(ymx, fmaxf(fmaxf(c.x, c.y), fmaxf(c.z, c.w)));
    }

    // warp reduce
    #pragma unroll
    for (int off = 16; off > 0; off >>= 1) {
        xmn = fminf(xmn, __shfl_xor_sync(0xFFFFFFFFu, xmn, off));
        xmx = fmaxf(xmx, __shfl_xor_sync(0xFFFFFFFFu, xmx, off));
        ymn = fminf(ymn, __shfl_xor_sync(0xFFFFFFFFu, ymn, off));
        ymx = fmaxf(ymx, __shfl_xor_sync(0xFFFFFFFFu, ymx, off));
    }

    if ((threadIdx.x & 31) == 0) {
        atomicMin(&g_bounds[b][0], f2o(xmn));
        atomicMax(&g_bounds[b][1], f2o(xmx));
        atomicMin(&g_bounds[b][2], f2o(ymn));
        atomicMax(&g_bounds[b][3], f2o(ymx));
    }
}

// Scatter: grid = (NS/(TPB*IT), B), block = TPB.
constexpr int TPB = 256;
constexpr int IT  = 8;

__global__ __launch_bounds__(TPB) void scatter_kernel(
    const float*  __restrict__ point_rates,
    const float2* __restrict__ coords,
    const float*  __restrict__ gia,
    float*        __restrict__ out)
{
    const int b = blockIdx.y;
    const float xmin = o2f(g_bounds[b][0]);
    const float xmax = o2f(g_bounds[b][1]);
    const float ymin = o2f(g_bounds[b][2]);
    const float ymax = o2f(g_bounds[b][3]);
    const float dx = __fsub_rn(xmax, xmin);
    const float dy = __fsub_rn(ymax, ymin);

    const float* pr = point_rates + (size_t)b * NS;
    const float* gb = gia + (size_t)b * HWSZ;
    float* ob = out + (size_t)b * HWSZ;

    const int base = blockIdx.x * (TPB * IT) + threadIdx.x;

    int   pix[IT];
    float rate[IT];
    bool  iv[IT];

    #pragma unroll
    for (int j = 0; j < IT; j++) {
        const int i = base + j * TPB;
        const float2 c = coords[i];
        rate[j] = pr[i];
        iv[j] = (c.x >= xmin) && (c.x <= xmax) && (c.y >= ymin) && (c.y <= ymax);
        // Match reference exactly: nx = (sx-xmin)/(xmax-xmin) in strict IEEE fp32,
        // then round-half-even of nx*(W-1).
        const float nx = __fdiv_rn(__fsub_rn(c.x, xmin), dx);
        const float ny = __fdiv_rn(__fsub_rn(c.y, ymin), dy);
        int px = __float2int_rn(__fmul_rn(nx, 255.0f));
        int py = __float2int_rn(__fmul_rn(ny, 255.0f));
        px = min(max(px, 0), WW - 1);
        py = min(max(py, 0), HH - 1);
        pix[j] = py * WW + px;
    }

    float gv[IT];
    #pragma unroll
    for (int j = 0; j < IT; j++) {
        gv[j] = __ldg(&gb[pix[j]]);     // 8 independent gathers in flight
    }

    #pragma unroll
    for (int j = 0; j < IT; j++) {
        if (iv[j]) {
            atomicAdd(&ob[pix[j]], __fmul_rn(rate[j], gv[j]));
        }
    }
}

extern "C" void kernel_launch(void* const* d_in, const int* in_sizes, int n_in,
                              void* d_out, int out_size)
{
    const float*  point_rates = (const float*)d_in[0];   // (B, NS)
    const float*  spatial     = (const float*)d_in[1];   // (B, 2, H, W)
    const float*  gia         = (const float*)d_in[2];   // (B, H, W)
    const float2* coords      = (const float2*)d_in[3];  // (NS, 2)
    float* out = (float*)d_out;                          // (B, 1, H, W)

    // 1) reset bounds scratch (graph replay safe)
    init_bounds_kernel<<<1, 32>>>();

    // 2) zero the output field
    cudaMemsetAsync(d_out, 0, (size_t)out_size * sizeof(float), 0);

    // 3) per-batch min/max of spatial
    dim3 mg(8, BB);
    minmax_kernel<<<mg, 256>>>(spatial);

    // 4) scatter-add
    dim3 sg(NS / (TPB * IT), BB);
    scatter_kernel<<<sg, TPB>>>(point_rates, coords, gia, out);
}

// round 2
// speedup vs baseline: 1.3303x; 1.3303x over previous
#include <cuda_runtime.h>
#include <cuda_bf16.h>
#include <cstdint>

// Problem constants
#define BB 32
#define NS 262144
#define HH 256
#define WW 256
#define HWSZ (HH * WW)

// Per-batch bounds: [b][0]=xmin,[1]=xmax,[2]=ymin,[3]=ymax (plain floats;
// written non-atomically by exactly one block per batch)
__device__ float g_bounds[BB][4];

// One block per batch (grid = BB, block = 512). Reduces both channels,
// writes final bounds directly — no init kernel, no atomics.
__global__ __launch_bounds__(512) void minmax_kernel(const float* __restrict__ spatial) {
    const int b = blockIdx.x;
    const float4* vx = reinterpret_cast<const float4*>(spatial + (size_t)b * 2 * HWSZ);
    const float4* vy = reinterpret_cast<const float4*>(spatial + (size_t)b * 2 * HWSZ + HWSZ);
    const int nvec = HWSZ / 4;   // 16384

    float xmn = 3.4e38f, xmx = -3.4e38f, ymn = 3.4e38f, ymx = -3.4e38f;

    for (int i = threadIdx.x; i < nvec; i += blockDim.x) {
        float4 a = vx[i];
        xmn = fminf(xmn, fminf(fminf(a.x, a.y), fminf(a.z, a.w)));
        xmx = fmaxf(xmx, fmaxf(fmaxf(a.x, a.y), fmaxf(a.z, a.w)));
        float4 c = vy[i];
        ymn = fminf(ymn, fminf(fminf(c.x, c.y), fminf(c.z, c.w)));
        ymx = fmaxf(ymx, fmaxf(fmaxf(c.x, c.y), fmaxf(c.z, c.w)));
    }

    // warp reduce
    #pragma unroll
    for (int off = 16; off > 0; off >>= 1) {
        xmn = fminf(xmn, __shfl_xor_sync(0xFFFFFFFFu, xmn, off));
        xmx = fmaxf(xmx, __shfl_xor_sync(0xFFFFFFFFu, xmx, off));
        ymn = fminf(ymn, __shfl_xor_sync(0xFFFFFFFFu, ymn, off));
        ymx = fmaxf(ymx, __shfl_xor_sync(0xFFFFFFFFu, ymx, off));
    }

    __shared__ float s[4][16];
    const int wid = threadIdx.x >> 5;
    const int lid = threadIdx.x & 31;
    if (lid == 0) {
        s[0][wid] = xmn; s[1][wid] = xmx; s[2][wid] = ymn; s[3][wid] = ymx;
    }
    __syncthreads();
    if (wid == 0) {
        const int nw = blockDim.x >> 5;   // 16
        float a = (lid < nw) ? s[0][lid] :  3.4e38f;
        float bmx = (lid < nw) ? s[1][lid] : -3.4e38f;
        float c = (lid < nw) ? s[2][lid] :  3.4e38f;
        float d = (lid < nw) ? s[3][lid] : -3.4e38f;
        #pragma unroll
        for (int off = 8; off > 0; off >>= 1) {
            a   = fminf(a,   __shfl_xor_sync(0xFFFFFFFFu, a,   off));
            bmx = fmaxf(bmx, __shfl_xor_sync(0xFFFFFFFFu, bmx, off));
            c   = fminf(c,   __shfl_xor_sync(0xFFFFFFFFu, c,   off));
            d   = fmaxf(d,   __shfl_xor_sync(0xFFFFFFFFu, d,   off));
        }
        if (lid == 0) {
            g_bounds[b][0] = a;
            g_bounds[b][1] = bmx;
            g_bounds[b][2] = c;
            g_bounds[b][3] = d;
        }
    }
}

// Scatter: accumulate ONLY point_rates (masked) into the field.
// The gia multiply is deferred to a streaming pass — this removes all
// random gathers from the hot loop (REDG is now the only random op).
constexpr int TPB = 256;
constexpr int IT  = 8;

__global__ __launch_bounds__(TPB) void scatter_kernel(
    const float*  __restrict__ point_rates,
    const float2* __restrict__ coords,
    float*        __restrict__ out)
{
    const int b = blockIdx.y;
    const float xmin = g_bounds[b][0];
    const float xmax = g_bounds[b][1];
    const float ymin = g_bounds[b][2];
    const float ymax = g_bounds[b][3];
    const float dx = __fsub_rn(xmax, xmin);
    const float dy = __fsub_rn(ymax, ymin);

    const float* pr = point_rates + (size_t)b * NS;
    float* ob = out + (size_t)b * HWSZ;

    const int base = blockIdx.x * (TPB * IT) + threadIdx.x;

    #pragma unroll
    for (int j = 0; j < IT; j++) {
        const int i = base + j * TPB;
        const float2 c = coords[i];
        const float rate = pr[i];
        const bool iv = (c.x >= xmin) && (c.x <= xmax) && (c.y >= ymin) && (c.y <= ymax);
        // Match reference bit-exactly: strict IEEE rn sub/div/mul, then
        // round-half-even (== jnp.round) before clip.
        const float nx = __fdiv_rn(__fsub_rn(c.x, xmin), dx);
        const float ny = __fdiv_rn(__fsub_rn(c.y, ymin), dy);
        int px = __float2int_rn(__fmul_rn(nx, 255.0f));
        int py = __float2int_rn(__fmul_rn(ny, 255.0f));
        px = min(max(px, 0), WW - 1);
        py = min(max(py, 0), HH - 1);
        if (iv) {
            atomicAdd(&ob[py * WW + px], rate);   // compiles to RED.ADD (no return)
        }
    }
}

// Streaming finalize: out[i] = rate_sum[i] * gia[i].  (B*H*W = 2M elems)
constexpr int MTPB = 256;
constexpr int MIT  = 4;   // float4 per thread iter

__global__ __launch_bounds__(MTPB) void mul_kernel(const float4* __restrict__ gia,
                                                   float4* __restrict__ out,
                                                   int n4)
{
    int i = blockIdx.x * MTPB + threadIdx.x;
    const int stride = gridDim.x * MTPB;
    for (; i < n4; i += stride) {
        float4 o = out[i];
        float4 g = gia[i];
        o.x = __fmul_rn(o.x, g.x);
        o.y = __fmul_rn(o.y, g.y);
        o.z = __fmul_rn(o.z, g.z);
        o.w = __fmul_rn(o.w, g.w);
        out[i] = o;
    }
}

extern "C" void kernel_launch(void* const* d_in, const int* in_sizes, int n_in,
                              void* d_out, int out_size)
{
    const float*  point_rates = (const float*)d_in[0];   // (B, NS)
    const float*  spatial     = (const float*)d_in[1];   // (B, 2, H, W)
    const float*  gia         = (const float*)d_in[2];   // (B, H, W)
    const float2* coords      = (const float2*)d_in[3];  // (NS, 2)
    float* out = (float*)d_out;                          // (B, 1, H, W)

    // 1) zero the accumulation field
    cudaMemsetAsync(d_out, 0, (size_t)out_size * sizeof(float), 0);

    // 2) per-batch min/max of spatial (one block per batch, no atomics)
    minmax_kernel<<<BB, 512>>>(spatial);

    // 3) scatter-add of masked rates (REDG only — no gathers)
    dim3 sg(NS / (TPB * IT), BB);
    scatter_kernel<<<sg, TPB>>>(point_rates, coords, out);

    // 4) finalize: multiply by gia
    const int n4 = (BB * HWSZ) / 4;   // 524288
    mul_kernel<<<n4 / (MTPB * MIT), MTPB>>>((const float4*)gia, (float4*)out, n4);
}